// round 1
// baseline (speedup 1.0000x reference)
#include <cuda_runtime.h>
#include <cuda_bf16.h>

// SNSCell: B=64 batch, S=512 sensory, N=512 state, M=128 motor, 6 unfolds, dt=0.1
// Strategy:
//   1) prefold_kernel: fold (sigma,mu,erev*mask,w*mask) -> float4 (k1,k0,ew,ww)
//      for both recurrent [N,N] and sensory [S,N] matrices (kills per-step RCPs,
//      turns 4 scalar loads into 1 LDG.128).
//   2) sensory_kernel: s_rev/s_w [B,N] reduction over S (done once).
//   3) 6x step_kernel: fused gated reduction over i + pointwise state update,
//      ping-pong state buffers in __device__ scratch. Tile: 32 cols x 8 batches
//      per CTA -> 128 CTAs (fills the chip), v-tile staged in smem (broadcast reads).
//   4) output_kernel: writes out[B,M] then v[B,N] into d_out.

#define Nn 512
#define Ss 512
#define Bb 64
#define Mm 128
#define UNFOLDS 6
#define DELTA (0.1f / 6.0f)

#define JT 32   // columns (j) per CTA
#define BT 8    // batches per CTA
#define KI 64   // i-chunk staged in smem
#define THREADS 128

// ---- device scratch (allocation-free) ----
__device__ float4 g_prm[Nn * Nn];    // recurrent folded params, [i][j]
__device__ float4 g_sprm[Ss * Nn];   // sensory folded params,   [s][n]
__device__ float  g_srev[Bb * Nn];
__device__ float  g_swsum[Bb * Nn];
__device__ float  g_v[2][Bb * Nn];   // ping-pong state

// ---------------------------------------------------------------- prefold
__global__ void prefold_kernel(const float* __restrict__ erev,
                               const float* __restrict__ w,
                               const float* __restrict__ sigma,
                               const float* __restrict__ mu,
                               const float* __restrict__ mask,
                               const float* __restrict__ serev,
                               const float* __restrict__ sw,
                               const float* __restrict__ ssigma,
                               const float* __restrict__ smu,
                               const float* __restrict__ smask)
{
    int idx = blockIdx.x * blockDim.x + threadIdx.x;
    if (idx >= Nn * Nn) return;   // S*N == N*N here
    {
        float s = sigma[idx], m = mu[idx], k = mask[idx];
        float k1 = 1.0f / (2.0f * s);
        g_prm[idx] = make_float4(k1, (s - m) * k1, erev[idx] * k, w[idx] * k);
    }
    {
        float s = ssigma[idx], m = smu[idx], k = smask[idx];
        float k1 = 1.0f / (2.0f * s);
        g_sprm[idx] = make_float4(k1, (s - m) * k1, serev[idx] * k, sw[idx] * k);
    }
}

// ---------------------------------------------------------------- sensory
__global__ __launch_bounds__(THREADS)
void sensory_kernel(const float* __restrict__ inputs,
                    const float* __restrict__ iw,
                    const float* __restrict__ ib)
{
    const int lane = threadIdx.x & 31;
    const int warp = threadIdx.x >> 5;           // 0..3
    const int j   = blockIdx.x * JT + lane;      // output column n
    const int b0  = blockIdx.y * BT;
    const int bb0 = warp * 2, bb1 = warp * 2 + 1;

    __shared__ float sx[BT][KI];

    float ar0 = 0.f, aw0 = 0.f, ar1 = 0.f, aw1 = 0.f;

    for (int s0 = 0; s0 < Ss; s0 += KI) {
        __syncthreads();
        for (int t = threadIdx.x; t < BT * KI; t += THREADS) {
            int bb = t / KI, ssi = t % KI;
            int sg = s0 + ssi;
            sx[bb][ssi] = fmaf(inputs[(b0 + bb) * Ss + sg], iw[sg], ib[sg]);
        }
        __syncthreads();
#pragma unroll 8
        for (int ii = 0; ii < KI; ii++) {
            float4 p = g_sprm[(s0 + ii) * Nn + j];
            float t0 = __saturatef(fmaf(sx[bb0][ii], p.x, p.y));
            float t1 = __saturatef(fmaf(sx[bb1][ii], p.x, p.y));
            ar0 = fmaf(t0, p.z, ar0);  aw0 = fmaf(t0, p.w, aw0);
            ar1 = fmaf(t1, p.z, ar1);  aw1 = fmaf(t1, p.w, aw1);
        }
    }
    g_srev [(b0 + bb0) * Nn + j] = ar0;
    g_swsum[(b0 + bb0) * Nn + j] = aw0;
    g_srev [(b0 + bb1) * Nn + j] = ar1;
    g_swsum[(b0 + bb1) * Nn + j] = aw1;
}

// ---------------------------------------------------------------- one unfold step
__global__ __launch_bounds__(THREADS)
void step_kernel(const float* __restrict__ ext_src,  // states on first step, else null
                 int src_sel, int dst_sel,
                 const float* __restrict__ tau,
                 const float* __restrict__ bias)
{
    const float* __restrict__ vsrc = ext_src ? ext_src : g_v[src_sel];
    float* __restrict__ vdst = g_v[dst_sel];

    const int lane = threadIdx.x & 31;
    const int warp = threadIdx.x >> 5;
    const int j   = blockIdx.x * JT + lane;
    const int b0  = blockIdx.y * BT;
    const int bb0 = warp * 2, bb1 = warp * 2 + 1;

    __shared__ float sv[BT][KI];

    float ar0 = 0.f, aw0 = 0.f, ar1 = 0.f, aw1 = 0.f;

    for (int i0 = 0; i0 < Nn; i0 += KI) {
        __syncthreads();
        for (int t = threadIdx.x; t < BT * KI; t += THREADS) {
            int bb = t / KI, ii = t % KI;
            sv[bb][ii] = vsrc[(b0 + bb) * Nn + i0 + ii];
        }
        __syncthreads();
#pragma unroll 8
        for (int ii = 0; ii < KI; ii++) {
            float4 p = g_prm[(i0 + ii) * Nn + j];
            float t0 = __saturatef(fmaf(sv[bb0][ii], p.x, p.y));
            float t1 = __saturatef(fmaf(sv[bb1][ii], p.x, p.y));
            ar0 = fmaf(t0, p.z, ar0);  aw0 = fmaf(t0, p.w, aw0);
            ar1 = fmaf(t1, p.z, ar1);  aw1 = fmaf(t1, p.w, aw1);
        }
    }

    const float tj = tau[j], bj = bias[j];
    {
        int g = (b0 + bb0) * Nn + j;
        float sum_rev = ar0 + g_srev[g] + bj;
        float sum_w   = aw0 + g_swsum[g];
        float k    = 1.0f / (1.0f + sum_w);
        float taun = tj * k;
        float q    = taun / (taun + DELTA);
        vdst[g] = q * vsrc[g] + (1.0f - q) * k * sum_rev;
    }
    {
        int g = (b0 + bb1) * Nn + j;
        float sum_rev = ar1 + g_srev[g] + bj;
        float sum_w   = aw1 + g_swsum[g];
        float k    = 1.0f / (1.0f + sum_w);
        float taun = tj * k;
        float q    = taun / (taun + DELTA);
        vdst[g] = q * vsrc[g] + (1.0f - q) * k * sum_rev;
    }
}

// ---------------------------------------------------------------- output
__global__ void output_kernel(int final_sel,
                              const float* __restrict__ ow,
                              const float* __restrict__ ob,
                              float* __restrict__ out)
{
    int idx = blockIdx.x * blockDim.x + threadIdx.x;
    if (idx >= Bb * Nn) return;
    int b = idx >> 9;          // /Nn
    int j = idx & (Nn - 1);
    float v = g_v[final_sel][idx];
    out[Bb * Mm + idx] = v;                       // second output: full state v
    if (j >= Nn - Mm) {
        int m = j - (Nn - Mm);
        out[b * Mm + m] = fmaf(v, ow[m], ob[m]);  // first output: motor slice
    }
}

// ---------------------------------------------------------------- launch
extern "C" void kernel_launch(void* const* d_in, const int* in_sizes, int n_in,
                              void* d_out, int out_size)
{
    const float* inputs = (const float*)d_in[0];
    const float* states = (const float*)d_in[1];
    const float* tau    = (const float*)d_in[2];
    const float* bias   = (const float*)d_in[3];
    const float* erev   = (const float*)d_in[4];
    const float* w      = (const float*)d_in[5];
    const float* sigma  = (const float*)d_in[6];
    const float* mu     = (const float*)d_in[7];
    const float* serev  = (const float*)d_in[8];
    const float* sw     = (const float*)d_in[9];
    const float* ssig   = (const float*)d_in[10];
    const float* smu    = (const float*)d_in[11];
    const float* mask   = (const float*)d_in[12];
    const float* smask  = (const float*)d_in[13];
    const float* iw     = (const float*)d_in[14];
    const float* ib     = (const float*)d_in[15];
    const float* ow     = (const float*)d_in[16];
    const float* ob     = (const float*)d_in[17];
    float* out = (float*)d_out;

    prefold_kernel<<<(Nn * Nn + 255) / 256, 256>>>(erev, w, sigma, mu, mask,
                                                   serev, sw, ssig, smu, smask);

    dim3 grid(Nn / JT, Bb / BT);   // 16 x 8 = 128 CTAs
    sensory_kernel<<<grid, THREADS>>>(inputs, iw, ib);

    // ping-pong: states -> g_v[0] -> g_v[1] -> ... (6 steps, final in g_v[1])
    int src = 1, dst = 0;
    step_kernel<<<grid, THREADS>>>(states, 0, dst, tau, bias);
    for (int s = 1; s < UNFOLDS; s++) {
        src = dst; dst = 1 - dst;
        step_kernel<<<grid, THREADS>>>(nullptr, src, dst, tau, bias);
    }

    output_kernel<<<(Bb * Nn + 255) / 256, 256>>>(dst, ow, ob, out);
}

// round 2
// speedup vs baseline: 2.0408x; 2.0408x over previous
#include <cuda_runtime.h>
#include <cuda_bf16.h>

// SNSCell: B=64, S=512, N=512, M=128, 6 unfolds, dt=0.1
// R2: occupancy fix. Step/sensory kernels: 256 CTAs x 256 threads
// (32 j-cols x 4 batches x 2 reduction-halves per CTA), v/x staged in smem
// ONCE before a sync-free main loop, split-K partials combined via smem.

#define Nn 512
#define Ss 512
#define Bb 64
#define Mm 128
#define UNFOLDS 6
#define DELTA (0.1f / 6.0f)

#define JT 32    // j columns per CTA (= lane)
#define BT 4     // batches per CTA
#define HALF 256 // i-range per warp (Nn/2)
#define THREADS 256

// ---- device scratch (allocation-free) ----
__device__ float4 g_prm[Nn * Nn];    // folded recurrent params [i][j]: (k1,k0,ew,ww)
__device__ float4 g_sprm[Ss * Nn];   // folded sensory params   [s][n]
__device__ float  g_srev[Bb * Nn];
__device__ float  g_swsum[Bb * Nn];
__device__ float  g_v[2][Bb * Nn];   // ping-pong state

// ---------------------------------------------------------------- prefold
__global__ void prefold_kernel(const float* __restrict__ erev,
                               const float* __restrict__ w,
                               const float* __restrict__ sigma,
                               const float* __restrict__ mu,
                               const float* __restrict__ mask,
                               const float* __restrict__ serev,
                               const float* __restrict__ sw,
                               const float* __restrict__ ssigma,
                               const float* __restrict__ smu,
                               const float* __restrict__ smask)
{
    int idx = blockIdx.x * blockDim.x + threadIdx.x;
    if (idx >= Nn * Nn) return;   // S*N == N*N here
    {
        float s = sigma[idx], m = mu[idx], k = mask[idx];
        float k1 = 1.0f / (2.0f * s);
        g_prm[idx] = make_float4(k1, (s - m) * k1, erev[idx] * k, w[idx] * k);
    }
    {
        float s = ssigma[idx], m = smu[idx], k = smask[idx];
        float k1 = 1.0f / (2.0f * s);
        g_sprm[idx] = make_float4(k1, (s - m) * k1, serev[idx] * k, sw[idx] * k);
    }
}

// ---------------------------------------------------------------- sensory
__global__ __launch_bounds__(THREADS)
void sensory_kernel(const float* __restrict__ inputs,
                    const float* __restrict__ iw,
                    const float* __restrict__ ib)
{
    const int lane = threadIdx.x & 31;
    const int warp = threadIdx.x >> 5;     // 0..7
    const int bb   = warp & 3;             // batch within CTA
    const int half = warp >> 2;            // i-range half
    const int j    = blockIdx.x * JT + lane;
    const int b0   = blockIdx.y * BT;

    __shared__ float sx[BT][Ss];
    __shared__ float red_r[8][JT];
    __shared__ float red_w[8][JT];

    // stage affine-mapped inputs for BT batches (once)
    for (int t = threadIdx.x; t < BT * Ss; t += THREADS) {
        int b = t >> 9, s = t & (Ss - 1);
        sx[b][s] = fmaf(inputs[(b0 + b) * Ss + s], iw[s], ib[s]);
    }
    __syncthreads();

    float ar = 0.f, aw = 0.f;
    const int sbase = half * HALF;
    const float* __restrict__ px = &sx[bb][sbase];
    const float4* __restrict__ pp = &g_sprm[sbase * Nn + j];
#pragma unroll 8
    for (int ii = 0; ii < HALF; ii++) {
        float4 p = pp[ii * Nn];
        float t = __saturatef(fmaf(px[ii], p.x, p.y));
        ar = fmaf(t, p.z, ar);
        aw = fmaf(t, p.w, aw);
    }

    red_r[warp][lane] = ar;
    red_w[warp][lane] = aw;
    __syncthreads();
    if (half == 0) {
        ar += red_r[warp + 4][lane];
        aw += red_w[warp + 4][lane];
        int g = (b0 + bb) * Nn + j;
        g_srev[g]  = ar;
        g_swsum[g] = aw;
    }
}

// ---------------------------------------------------------------- one unfold step
__global__ __launch_bounds__(THREADS)
void step_kernel(const float* __restrict__ ext_src,  // states on first step, else null
                 int src_sel, int dst_sel,
                 const float* __restrict__ tau,
                 const float* __restrict__ bias)
{
    const float* __restrict__ vsrc = ext_src ? ext_src : g_v[src_sel];
    float* __restrict__ vdst = g_v[dst_sel];

    const int lane = threadIdx.x & 31;
    const int warp = threadIdx.x >> 5;
    const int bb   = warp & 3;
    const int half = warp >> 2;
    const int j    = blockIdx.x * JT + lane;
    const int b0   = blockIdx.y * BT;

    __shared__ float sv[BT][Nn];
    __shared__ float red_r[8][JT];
    __shared__ float red_w[8][JT];

    // stage v for BT batches (vectorized, once)
    {
        const float4* src4 = (const float4*)(vsrc + b0 * Nn);
        float4* dst4 = (float4*)&sv[0][0];
        for (int t = threadIdx.x; t < BT * Nn / 4; t += THREADS)
            dst4[t] = src4[t];
    }
    __syncthreads();

    float ar = 0.f, aw = 0.f;
    const int ibase = half * HALF;
    const float* __restrict__ pv = &sv[bb][ibase];
    const float4* __restrict__ pp = &g_prm[ibase * Nn + j];
#pragma unroll 8
    for (int ii = 0; ii < HALF; ii++) {
        float4 p = pp[ii * Nn];
        float t = __saturatef(fmaf(pv[ii], p.x, p.y));
        ar = fmaf(t, p.z, ar);
        aw = fmaf(t, p.w, aw);
    }

    red_r[warp][lane] = ar;
    red_w[warp][lane] = aw;
    __syncthreads();
    if (half == 0) {
        ar += red_r[warp + 4][lane];
        aw += red_w[warp + 4][lane];
        int g = (b0 + bb) * Nn + j;
        float sum_rev = ar + g_srev[g] + bias[j];
        float sum_w   = aw + g_swsum[g];
        float k    = 1.0f / (1.0f + sum_w);
        float taun = tau[j] * k;
        float q    = taun / (taun + DELTA);
        vdst[g] = q * sv[bb][j] + (1.0f - q) * k * sum_rev;
    }
}

// ---------------------------------------------------------------- output
__global__ void output_kernel(int final_sel,
                              const float* __restrict__ ow,
                              const float* __restrict__ ob,
                              float* __restrict__ out)
{
    int idx = blockIdx.x * blockDim.x + threadIdx.x;
    if (idx >= Bb * Nn) return;
    int b = idx >> 9;          // /Nn
    int j = idx & (Nn - 1);
    float v = g_v[final_sel][idx];
    out[Bb * Mm + idx] = v;                       // second output: full state v
    if (j >= Nn - Mm) {
        int m = j - (Nn - Mm);
        out[b * Mm + m] = fmaf(v, ow[m], ob[m]);  // first output: motor slice
    }
}

// ---------------------------------------------------------------- launch
extern "C" void kernel_launch(void* const* d_in, const int* in_sizes, int n_in,
                              void* d_out, int out_size)
{
    const float* inputs = (const float*)d_in[0];
    const float* states = (const float*)d_in[1];
    const float* tau    = (const float*)d_in[2];
    const float* bias   = (const float*)d_in[3];
    const float* erev   = (const float*)d_in[4];
    const float* w      = (const float*)d_in[5];
    const float* sigma  = (const float*)d_in[6];
    const float* mu     = (const float*)d_in[7];
    const float* serev  = (const float*)d_in[8];
    const float* sw     = (const float*)d_in[9];
    const float* ssig   = (const float*)d_in[10];
    const float* smu    = (const float*)d_in[11];
    const float* mask   = (const float*)d_in[12];
    const float* smask  = (const float*)d_in[13];
    const float* iw     = (const float*)d_in[14];
    const float* ib     = (const float*)d_in[15];
    const float* ow     = (const float*)d_in[16];
    const float* ob     = (const float*)d_in[17];
    float* out = (float*)d_out;

    prefold_kernel<<<(Nn * Nn + 255) / 256, 256>>>(erev, w, sigma, mu, mask,
                                                   serev, sw, ssig, smu, smask);

    dim3 grid(Nn / JT, Bb / BT);   // 16 x 16 = 256 CTAs
    sensory_kernel<<<grid, THREADS>>>(inputs, iw, ib);

    // ping-pong: states -> g_v[0] -> g_v[1] -> ...
    int src = 1, dst = 0;
    step_kernel<<<grid, THREADS>>>(states, 0, dst, tau, bias);
    for (int s = 1; s < UNFOLDS; s++) {
        src = dst; dst = 1 - dst;
        step_kernel<<<grid, THREADS>>>(nullptr, src, dst, tau, bias);
    }

    output_kernel<<<(Bb * Nn + 255) / 256, 256>>>(dst, ow, ob, out);
}

// round 3
// speedup vs baseline: 6.2304x; 3.0530x over previous
#include <cuda_runtime.h>
#include <cuda_bf16.h>

// SNSCell: B=64, S=512, N=512, M=128, 6 unfolds, dt=0.1
// R3: intensity + MLP fix. Step/sensory: grid (16 j-tiles, 8 batch-tiles),
// 512 threads = 16 warps splitting the i-reduction 16-way. Each thread keeps
// 16 accumulators (8 batches x {rev,w}) so every float4 param load feeds
// 8 batches of math. v staged transposed in smem (svT[i][b]) -> 2 broadcast
// LDS.128 per iteration. Reduction buffer aliases svT.

#define Nn 512
#define Ss 512
#define Bb 64
#define Mm 128
#define UNFOLDS 6
#define DELTA (0.1f / 6.0f)

#define JT 32      // j columns per CTA (= lane)
#define BT 8       // batches per CTA (accumulated per-thread)
#define ISPLIT 16  // warps splitting the i range
#define ICHUNK (Nn / ISPLIT)   // 32
#define THREADS 512

// ---- device scratch (allocation-free) ----
__device__ float4 g_prm[Nn * Nn];    // folded recurrent params [i][j]: (k1,k0,ew,ww)
__device__ float4 g_sprm[Ss * Nn];   // folded sensory params   [s][n]
__device__ float  g_srev[Bb * Nn];
__device__ float  g_swsum[Bb * Nn];
__device__ float  g_v[2][Bb * Nn];   // ping-pong state

// ---------------------------------------------------------------- prefold
__global__ void prefold_kernel(const float* __restrict__ erev,
                               const float* __restrict__ w,
                               const float* __restrict__ sigma,
                               const float* __restrict__ mu,
                               const float* __restrict__ mask,
                               const float* __restrict__ serev,
                               const float* __restrict__ sw,
                               const float* __restrict__ ssigma,
                               const float* __restrict__ smu,
                               const float* __restrict__ smask)
{
    int idx = blockIdx.x * blockDim.x + threadIdx.x;
    if (idx >= Nn * Nn) return;   // S*N == N*N here
    {
        float s = sigma[idx], m = mu[idx], k = mask[idx];
        float k1 = 1.0f / (2.0f * s);
        g_prm[idx] = make_float4(k1, (s - m) * k1, erev[idx] * k, w[idx] * k);
    }
    {
        float s = ssigma[idx], m = smu[idx], k = smask[idx];
        float k1 = 1.0f / (2.0f * s);
        g_sprm[idx] = make_float4(k1, (s - m) * k1, serev[idx] * k, sw[idx] * k);
    }
}

// ---------------------------------------------------------------- sensory
__global__ __launch_bounds__(THREADS)
void sensory_kernel(const float* __restrict__ inputs,
                    const float* __restrict__ iw,
                    const float* __restrict__ ib)
{
    __shared__ __align__(16) char smem_raw[ISPLIT * BT * JT * sizeof(float2)]; // 32KB
    float  (*sxT)[BT]       = reinterpret_cast<float(*)[BT]>(smem_raw);        // [Ss][BT]
    float2 (*red)[BT][JT]   = reinterpret_cast<float2(*)[BT][JT]>(smem_raw);

    const int lane = threadIdx.x & 31;
    const int warp = threadIdx.x >> 5;     // 0..15
    const int j    = blockIdx.x * JT + lane;
    const int b0   = blockIdx.y * BT;

    // stage affine-mapped inputs, transposed: sxT[s][b]
    {
        int s = threadIdx.x;               // THREADS == Ss
        float wv = iw[s], bv = ib[s];
#pragma unroll
        for (int b = 0; b < BT; b++)
            sxT[s][b] = fmaf(inputs[(b0 + b) * Ss + s], wv, bv);
    }
    __syncthreads();

    float ar[BT], aw[BT];
#pragma unroll
    for (int b = 0; b < BT; b++) { ar[b] = 0.f; aw[b] = 0.f; }

    const int sbase = warp * ICHUNK;
#pragma unroll 8
    for (int ii = 0; ii < ICHUNK; ii++) {
        int s = sbase + ii;
        float4 p  = g_sprm[s * Nn + j];
        float4 va = *(const float4*)&sxT[s][0];
        float4 vb = *(const float4*)&sxT[s][4];
        float t;
        t = __saturatef(fmaf(va.x, p.x, p.y)); ar[0] = fmaf(t, p.z, ar[0]); aw[0] = fmaf(t, p.w, aw[0]);
        t = __saturatef(fmaf(va.y, p.x, p.y)); ar[1] = fmaf(t, p.z, ar[1]); aw[1] = fmaf(t, p.w, aw[1]);
        t = __saturatef(fmaf(va.z, p.x, p.y)); ar[2] = fmaf(t, p.z, ar[2]); aw[2] = fmaf(t, p.w, aw[2]);
        t = __saturatef(fmaf(va.w, p.x, p.y)); ar[3] = fmaf(t, p.z, ar[3]); aw[3] = fmaf(t, p.w, aw[3]);
        t = __saturatef(fmaf(vb.x, p.x, p.y)); ar[4] = fmaf(t, p.z, ar[4]); aw[4] = fmaf(t, p.w, aw[4]);
        t = __saturatef(fmaf(vb.y, p.x, p.y)); ar[5] = fmaf(t, p.z, ar[5]); aw[5] = fmaf(t, p.w, aw[5]);
        t = __saturatef(fmaf(vb.z, p.x, p.y)); ar[6] = fmaf(t, p.z, ar[6]); aw[6] = fmaf(t, p.w, aw[6]);
        t = __saturatef(fmaf(vb.w, p.x, p.y)); ar[7] = fmaf(t, p.z, ar[7]); aw[7] = fmaf(t, p.w, aw[7]);
    }

    __syncthreads();   // everyone done reading sxT before red aliases it
#pragma unroll
    for (int b = 0; b < BT; b++)
        red[warp][b][lane] = make_float2(ar[b], aw[b]);
    __syncthreads();

    if (warp < BT) {   // warp = batch
        float sr = 0.f, sw2 = 0.f;
#pragma unroll
        for (int ww = 0; ww < ISPLIT; ww++) {
            float2 r = red[ww][warp][lane];
            sr += r.x; sw2 += r.y;
        }
        int g = (b0 + warp) * Nn + j;
        g_srev[g]  = sr;
        g_swsum[g] = sw2;
    }
}

// ---------------------------------------------------------------- one unfold step
__global__ __launch_bounds__(THREADS)
void step_kernel(const float* __restrict__ ext_src,  // states on first step, else null
                 int src_sel, int dst_sel,
                 const float* __restrict__ tau,
                 const float* __restrict__ bias)
{
    const float* __restrict__ vsrc = ext_src ? ext_src : g_v[src_sel];
    float* __restrict__ vdst = g_v[dst_sel];

    __shared__ __align__(16) char smem_raw[ISPLIT * BT * JT * sizeof(float2)]; // 32KB
    float  (*svT)[BT]     = reinterpret_cast<float(*)[BT]>(smem_raw);          // [Nn][BT]
    float2 (*red)[BT][JT] = reinterpret_cast<float2(*)[BT][JT]>(smem_raw);

    const int lane = threadIdx.x & 31;
    const int warp = threadIdx.x >> 5;     // 0..15
    const int j    = blockIdx.x * JT + lane;
    const int b0   = blockIdx.y * BT;

    // stage v transposed: svT[i][b]
    {
        int i = threadIdx.x;               // THREADS == Nn
#pragma unroll
        for (int b = 0; b < BT; b++)
            svT[i][b] = vsrc[(b0 + b) * Nn + i];
    }
    __syncthreads();

    // pre-read old v for the epilogue (before red aliases svT)
    float vold = (warp < BT) ? svT[j][warp] : 0.f;

    float ar[BT], aw[BT];
#pragma unroll
    for (int b = 0; b < BT; b++) { ar[b] = 0.f; aw[b] = 0.f; }

    const int ibase = warp * ICHUNK;
#pragma unroll 8
    for (int ii = 0; ii < ICHUNK; ii++) {
        int i = ibase + ii;
        float4 p  = g_prm[i * Nn + j];
        float4 va = *(const float4*)&svT[i][0];
        float4 vb = *(const float4*)&svT[i][4];
        float t;
        t = __saturatef(fmaf(va.x, p.x, p.y)); ar[0] = fmaf(t, p.z, ar[0]); aw[0] = fmaf(t, p.w, aw[0]);
        t = __saturatef(fmaf(va.y, p.x, p.y)); ar[1] = fmaf(t, p.z, ar[1]); aw[1] = fmaf(t, p.w, aw[1]);
        t = __saturatef(fmaf(va.z, p.x, p.y)); ar[2] = fmaf(t, p.z, ar[2]); aw[2] = fmaf(t, p.w, aw[2]);
        t = __saturatef(fmaf(va.w, p.x, p.y)); ar[3] = fmaf(t, p.z, ar[3]); aw[3] = fmaf(t, p.w, aw[3]);
        t = __saturatef(fmaf(vb.x, p.x, p.y)); ar[4] = fmaf(t, p.z, ar[4]); aw[4] = fmaf(t, p.w, aw[4]);
        t = __saturatef(fmaf(vb.y, p.x, p.y)); ar[5] = fmaf(t, p.z, ar[5]); aw[5] = fmaf(t, p.w, aw[5]);
        t = __saturatef(fmaf(vb.z, p.x, p.y)); ar[6] = fmaf(t, p.z, ar[6]); aw[6] = fmaf(t, p.w, aw[6]);
        t = __saturatef(fmaf(vb.w, p.x, p.y)); ar[7] = fmaf(t, p.z, ar[7]); aw[7] = fmaf(t, p.w, aw[7]);
    }

    __syncthreads();   // done reading svT before red aliases it
#pragma unroll
    for (int b = 0; b < BT; b++)
        red[warp][b][lane] = make_float2(ar[b], aw[b]);
    __syncthreads();

    if (warp < BT) {   // warp = batch
        float sr = 0.f, sw2 = 0.f;
#pragma unroll
        for (int ww = 0; ww < ISPLIT; ww++) {
            float2 r = red[ww][warp][lane];
            sr += r.x; sw2 += r.y;
        }
        int g = (b0 + warp) * Nn + j;
        float sum_rev = sr + g_srev[g] + bias[j];
        float sum_w   = sw2 + g_swsum[g];
        float k    = 1.0f / (1.0f + sum_w);
        float taun = tau[j] * k;
        float q    = taun / (taun + DELTA);
        vdst[g] = q * vold + (1.0f - q) * k * sum_rev;
    }
}

// ---------------------------------------------------------------- output
__global__ void output_kernel(int final_sel,
                              const float* __restrict__ ow,
                              const float* __restrict__ ob,
                              float* __restrict__ out)
{
    int idx = blockIdx.x * blockDim.x + threadIdx.x;
    if (idx >= Bb * Nn) return;
    int b = idx >> 9;          // /Nn
    int j = idx & (Nn - 1);
    float v = g_v[final_sel][idx];
    out[Bb * Mm + idx] = v;                       // second output: full state v
    if (j >= Nn - Mm) {
        int m = j - (Nn - Mm);
        out[b * Mm + m] = fmaf(v, ow[m], ob[m]);  // first output: motor slice
    }
}

// ---------------------------------------------------------------- launch
extern "C" void kernel_launch(void* const* d_in, const int* in_sizes, int n_in,
                              void* d_out, int out_size)
{
    const float* inputs = (const float*)d_in[0];
    const float* states = (const float*)d_in[1];
    const float* tau    = (const float*)d_in[2];
    const float* bias   = (const float*)d_in[3];
    const float* erev   = (const float*)d_in[4];
    const float* w      = (const float*)d_in[5];
    const float* sigma  = (const float*)d_in[6];
    const float* mu     = (const float*)d_in[7];
    const float* serev  = (const float*)d_in[8];
    const float* sw     = (const float*)d_in[9];
    const float* ssig   = (const float*)d_in[10];
    const float* smu    = (const float*)d_in[11];
    const float* mask   = (const float*)d_in[12];
    const float* smask  = (const float*)d_in[13];
    const float* iw     = (const float*)d_in[14];
    const float* ib     = (const float*)d_in[15];
    const float* ow     = (const float*)d_in[16];
    const float* ob     = (const float*)d_in[17];
    float* out = (float*)d_out;

    prefold_kernel<<<(Nn * Nn + 255) / 256, 256>>>(erev, w, sigma, mu, mask,
                                                   serev, sw, ssig, smu, smask);

    dim3 grid(Nn / JT, Bb / BT);   // 16 x 8 = 128 CTAs
    sensory_kernel<<<grid, THREADS>>>(inputs, iw, ib);

    // ping-pong: states -> g_v[0] -> g_v[1] -> ...
    int src = 1, dst = 0;
    step_kernel<<<grid, THREADS>>>(states, 0, dst, tau, bias);
    for (int s = 1; s < UNFOLDS; s++) {
        src = dst; dst = 1 - dst;
        step_kernel<<<grid, THREADS>>>(nullptr, src, dst, tau, bias);
    }

    output_kernel<<<(Bb * Nn + 255) / 256, 256>>>(dst, ow, ob, out);
}

// round 4
// speedup vs baseline: 6.3121x; 1.0131x over previous
#include <cuda_runtime.h>

// SNSCell: B=64, S=512, N=512, M=128, 6 unfolds, dt=0.1
// R4: single persistent kernel (sensory + 6 steps + output) with per-batch-group
// software barriers. Tile: warp = 16 j-cols x 2 batch-halves (lane = jl + 16*bh),
// CTA = 16 j x 16 batches, grid (32 j-tiles, 4 b-tiles) = 128 CTAs (all resident).
// Each param float4 feeds 16 batches (traffic 16MB/step). Sensory sums, tau, bias
// live in registers across all steps. v re-reads use __ldcg (L1 stale within launch).

#define Nn 512
#define Ss 512
#define Bb 64
#define Mm 128
#define UNFOLDS 6
#define DELTA (0.1f / 6.0f)

#define JT 16      // j columns per CTA
#define BT 16      // batches per CTA
#define THREADS 512
#define NWARP 16
#define ICHUNK (Nn / NWARP)    // 32 i's per warp
#define GRPX 32                // CTAs per barrier group (j-tiles of one b-tile)

// ---- device scratch (allocation-free) ----
__device__ float4 g_prm[Nn * Nn];    // folded recurrent params [i][j]: (k1,k0,ew,ww)
__device__ float4 g_sprm[Ss * Nn];   // folded sensory params   [s][n]
__device__ float  g_v[2][Bb * Nn];   // ping-pong state
__device__ unsigned g_bar[4 * 32];   // per-group barrier counters (128B apart)

// ---------------------------------------------------------------- prefold
__global__ void prefold_kernel(const float* __restrict__ erev,
                               const float* __restrict__ w,
                               const float* __restrict__ sigma,
                               const float* __restrict__ mu,
                               const float* __restrict__ mask,
                               const float* __restrict__ serev,
                               const float* __restrict__ sw,
                               const float* __restrict__ ssigma,
                               const float* __restrict__ smu,
                               const float* __restrict__ smask)
{
    int idx = blockIdx.x * blockDim.x + threadIdx.x;
    if (idx < 4 * 32) g_bar[idx] = 0;          // reset barriers every replay
    if (idx >= Nn * Nn) return;                // S*N == N*N here
    {
        float s = sigma[idx], m = mu[idx], k = mask[idx];
        float k1 = 1.0f / (2.0f * s);
        g_prm[idx] = make_float4(k1, (s - m) * k1, erev[idx] * k, w[idx] * k);
    }
    {
        float s = ssigma[idx], m = smu[idx], k = smask[idx];
        float k1 = 1.0f / (2.0f * s);
        g_sprm[idx] = make_float4(k1, (s - m) * k1, serev[idx] * k, sw[idx] * k);
    }
}

// ---------------------------------------------------------------- persistent cell
__global__ __launch_bounds__(THREADS, 1)
void sns_persistent(const float* __restrict__ inputs,
                    const float* __restrict__ states,
                    const float* __restrict__ tau,
                    const float* __restrict__ bias,
                    const float* __restrict__ iw,
                    const float* __restrict__ ib,
                    const float* __restrict__ ow,
                    const float* __restrict__ ob,
                    float* __restrict__ out)
{
    __shared__ __align__(16) float smem[BT * Nn];                       // 32KB
    float  (*sT)[Nn]      = reinterpret_cast<float(*)[Nn]>(smem);       // [b][i]
    float2 (*red)[BT][JT] = reinterpret_cast<float2(*)[BT][JT]>(smem);  // alias

    const int tid  = threadIdx.x;
    const int lane = tid & 31;
    const int warp = tid >> 5;          // 0..15 (also: epilogue batch index)
    const int jl   = lane & 15;
    const int bh   = lane >> 4;         // batch half: 0 -> b 0..7, 1 -> b 8..15
    const int j    = blockIdx.x * JT + jl;
    const int b0   = blockIdx.y * BT;
    unsigned* bar  = &g_bar[blockIdx.y * 32];

    const float tauj  = tau[j];
    const float biasj = bias[j];

    float srev = 0.f, swsum = 0.f;      // sensory sums, held in registers (lane<16)

    // ================= sensory phase (no global writes) =================
    {
        float wv = iw[tid], bv = ib[tid];
#pragma unroll
        for (int b = 0; b < BT; b++)
            sT[b][tid] = fmaf(inputs[(b0 + b) * Ss + tid], wv, bv);
    }
    __syncthreads();
    {
        float ar[8], aw[8];
#pragma unroll
        for (int k = 0; k < 8; k++) { ar[k] = 0.f; aw[k] = 0.f; }
        const float4* __restrict__ pp = g_sprm + (warp * ICHUNK) * Nn + j;
#pragma unroll 4
        for (int ii = 0; ii < ICHUNK; ii++) {
            int i = warp * ICHUNK + ii;
            float4 p = pp[ii * Nn];
#pragma unroll
            for (int k = 0; k < 8; k++) {
                float t = __saturatef(fmaf(sT[bh * 8 + k][i], p.x, p.y));
                ar[k] = fmaf(t, p.z, ar[k]);
                aw[k] = fmaf(t, p.w, aw[k]);
            }
        }
        __syncthreads();
#pragma unroll
        for (int k = 0; k < 8; k++)
            red[warp][bh * 8 + k][jl] = make_float2(ar[k], aw[k]);
        __syncthreads();
        if (lane < 16) {
            float sr = 0.f, sw2 = 0.f;
#pragma unroll
            for (int ww = 0; ww < NWARP; ww++) {
                float2 r = red[ww][warp][jl];
                sr += r.x; sw2 += r.y;
            }
            srev = sr; swsum = sw2;
        }
        __syncthreads();   // red reads done before step-1 staging reuses smem
    }

    // ================= 6 unfold steps =================
    const float* vsrc = states;
    unsigned target = GRPX;
    for (int s = 1; s <= UNFOLDS; s++) {
        // stage v[b][i] (bypass L1: written by peer CTAs within this launch)
#pragma unroll
        for (int b = 0; b < BT; b++)
            sT[b][tid] = __ldcg(&vsrc[(b0 + b) * Nn + tid]);
        __syncthreads();

        float vold = sT[warp][j];   // used by lane<16 epilogue

        float ar[8], aw[8];
#pragma unroll
        for (int k = 0; k < 8; k++) { ar[k] = 0.f; aw[k] = 0.f; }
        const float4* __restrict__ pp = g_prm + (warp * ICHUNK) * Nn + j;
#pragma unroll 4
        for (int ii = 0; ii < ICHUNK; ii++) {
            int i = warp * ICHUNK + ii;
            float4 p = pp[ii * Nn];
#pragma unroll
            for (int k = 0; k < 8; k++) {
                float t = __saturatef(fmaf(sT[bh * 8 + k][i], p.x, p.y));
                ar[k] = fmaf(t, p.z, ar[k]);
                aw[k] = fmaf(t, p.w, aw[k]);
            }
        }
        __syncthreads();
#pragma unroll
        for (int k = 0; k < 8; k++)
            red[warp][bh * 8 + k][jl] = make_float2(ar[k], aw[k]);
        __syncthreads();

        float* vdst = g_v[(s - 1) & 1];
        if (lane < 16) {
            float sr = srev + biasj, sw2 = swsum;
#pragma unroll
            for (int ww = 0; ww < NWARP; ww++) {
                float2 r = red[ww][warp][jl];
                sr += r.x; sw2 += r.y;
            }
            float kk   = 1.0f / (1.0f + sw2);
            float tn   = tauj * kk;
            float q    = tn / (tn + DELTA);
            float vnew = q * vold + (1.0f - q) * kk * sr;
            if (s < UNFOLDS) {
                vdst[(b0 + warp) * Nn + j] = vnew;
            } else {
                out[Bb * Mm + (b0 + warp) * Nn + j] = vnew;   // state output
                if (j >= Nn - Mm) {
                    int m = j - (Nn - Mm);
                    out[(b0 + warp) * Mm + m] = fmaf(vnew, ow[m], ob[m]);
                }
            }
        }

        if (s < UNFOLDS) {
            __threadfence();            // make vdst writes visible (release)
            __syncthreads();
            if (tid == 0) {
                atomicAdd(bar, 1u);
                volatile unsigned* vb = bar;
                while (*vb < target) { }
            }
            __syncthreads();            // all threads held until group done
            target += GRPX;
            vsrc = vdst;
        }
    }
}

// ---------------------------------------------------------------- launch
extern "C" void kernel_launch(void* const* d_in, const int* in_sizes, int n_in,
                              void* d_out, int out_size)
{
    const float* inputs = (const float*)d_in[0];
    const float* states = (const float*)d_in[1];
    const float* tau    = (const float*)d_in[2];
    const float* bias   = (const float*)d_in[3];
    const float* erev   = (const float*)d_in[4];
    const float* w      = (const float*)d_in[5];
    const float* sigma  = (const float*)d_in[6];
    const float* mu     = (const float*)d_in[7];
    const float* serev  = (const float*)d_in[8];
    const float* sw     = (const float*)d_in[9];
    const float* ssig   = (const float*)d_in[10];
    const float* smu    = (const float*)d_in[11];
    const float* mask   = (const float*)d_in[12];
    const float* smask  = (const float*)d_in[13];
    const float* iw     = (const float*)d_in[14];
    const float* ib     = (const float*)d_in[15];
    const float* ow     = (const float*)d_in[16];
    const float* ob     = (const float*)d_in[17];
    float* out = (float*)d_out;

    prefold_kernel<<<(Nn * Nn + 255) / 256, 256>>>(erev, w, sigma, mu, mask,
                                                   serev, sw, ssig, smu, smask);

    dim3 grid(Nn / JT, Bb / BT);   // 32 x 4 = 128 CTAs, all co-resident
    sns_persistent<<<grid, THREADS>>>(inputs, states, tau, bias,
                                      iw, ib, ow, ob, out);
}